// round 1
// baseline (speedup 1.0000x reference)
#include <cuda_runtime.h>
#include <cstdint>

#define T_STEPS 512
#define BATCH   32
#define HID     512
#define G4      2048              // 4*H
#define NBLK    128
#define STRIDE  516               // padded k-stride (floats) for smem tiles
#define SECT    ((size_t)2 * T_STEPS * BATCH * HID)   // L*T*B*H

// ---------------- device scratch (no allocations allowed) ----------------
__device__ float    g_pre[(size_t)T_STEPS * BATCH * G4];   // 134 MB: pre-projection for current layer
__device__ unsigned g_bar;

__global__ void reset_bar() { g_bar = 0u; }

// ---------------- pre-projection GEMM:  g_pre[row][g] = sum_k A[row][k]*W[g][k] + bias[g] ---------
// A: [16384 x 512] row-major, W: [2048 x 512] row-major (w_ih layout as given)
__global__ void __launch_bounds__(256) pre_gemm(
    const float* __restrict__ A, const float* __restrict__ W,
    const float* __restrict__ bih, const float* __restrict__ bhh)
{
    __shared__ float As[16][68];
    __shared__ float Ws[16][68];
    const int tid  = threadIdx.x;
    const int brow = blockIdx.x * 64;
    const int bcol = blockIdx.y * 64;
    const int lr = tid >> 2;            // 0..63
    const int lc = (tid & 3) << 2;      // 0,4,8,12
    const int tm = (tid >> 4) << 2;     // 0..60
    const int tn = (tid & 15) << 2;     // 0..60

    float acc[4][4];
#pragma unroll
    for (int i = 0; i < 4; i++)
#pragma unroll
        for (int j = 0; j < 4; j++) acc[i][j] = 0.f;

    for (int k0 = 0; k0 < HID; k0 += 16) {
        float4 a4 = *(const float4*)&A[(size_t)(brow + lr) * HID + k0 + lc];
        float4 w4 = *(const float4*)&W[(size_t)(bcol + lr) * HID + k0 + lc];
        __syncthreads();
        As[lc + 0][lr] = a4.x; As[lc + 1][lr] = a4.y; As[lc + 2][lr] = a4.z; As[lc + 3][lr] = a4.w;
        Ws[lc + 0][lr] = w4.x; Ws[lc + 1][lr] = w4.y; Ws[lc + 2][lr] = w4.z; Ws[lc + 3][lr] = w4.w;
        __syncthreads();
#pragma unroll
        for (int kk = 0; kk < 16; kk++) {
            float4 am = *(const float4*)&As[kk][tm];
            float4 wn = *(const float4*)&Ws[kk][tn];
            float amv[4] = {am.x, am.y, am.z, am.w};
            float wnv[4] = {wn.x, wn.y, wn.z, wn.w};
#pragma unroll
            for (int i = 0; i < 4; i++)
#pragma unroll
                for (int j = 0; j < 4; j++) acc[i][j] += amv[i] * wnv[j];
        }
    }
    float bv[4];
#pragma unroll
    for (int j = 0; j < 4; j++) { int g = bcol + tn + j; bv[j] = bih[g] + bhh[g]; }
#pragma unroll
    for (int i = 0; i < 4; i++) {
        float4 o = make_float4(acc[i][0] + bv[0], acc[i][1] + bv[1],
                               acc[i][2] + bv[2], acc[i][3] + bv[3]);
        *(float4*)&g_pre[(size_t)(brow + tm + i) * G4 + bcol + tn] = o;
    }
}

// ---------------- persistent recurrence kernel (one launch per layer) ----------------
// Block jblk owns hidden indices j in [jblk*4, jblk*4+4), all 4 gates, all 32 batch rows.
// Whh slice (16 gate-cols x 512) stays in SMEM for the whole layer.
// Per step: stage h_{t-1} (32x512) in SMEM, 256 threads = 16 cols x 16 k-chunks,
// each thread accumulates 32 batch dot-partials, smem-reduce, activate, write 6 outputs,
// spin grid barrier.
__global__ void __launch_bounds__(256, 1) lstm_layer(
    int layer, const float* __restrict__ whh, float* __restrict__ out)
{
    extern __shared__ float sm[];
    float* w_s  = sm;                   // [16][STRIDE]  w_s[c*STRIDE + k]
    float* h_s  = sm + 16 * STRIDE;     // [32][STRIDE]  h_s[b*STRIDE + k]
    float* part = h_s;                  // overlay: [16][STRIDE] part[ks*STRIDE + b4*64 + c*4 + u]

    const int tid  = threadIdx.x;
    const int col  = tid & 15;          // 0..15 : (gate g = col>>2, jj = col&3)
    const int ksub = tid >> 4;          // 0..15 : k chunk of 32
    const int jblk = blockIdx.x;

    // Load Whh slice once (coalesced over k).
    for (int i = tid; i < 16 * 128; i += 256) {
        int c  = i >> 7;
        int kq = (i & 127) << 2;
        int gc = (c >> 2) * HID + jblk * 4 + (c & 3);
        *(float4*)&w_s[c * STRIDE + kq] = *(const float4*)&whh[(size_t)gc * HID + kq];
    }

    // Activation-thread persistent state (threads 0..127 own a fixed (b,j) pair).
    const int ajj = tid & 3;
    const int ab  = tid >> 2;
    float c_state = 0.f;

    unsigned phase = 0;
    for (int t = 0; t < T_STEPS; t++) {
        // ---- stage h_{t-1} ----
        if (t == 0) {
            for (int i = tid; i < 32 * 128; i += 256) {
                int b = i >> 7; int kq = (i & 127) << 2;
                *(float4*)&h_s[b * STRIDE + kq] = make_float4(0.f, 0.f, 0.f, 0.f);
            }
        } else {
            const float* hp = out + ((size_t)(layer * T_STEPS + (t - 1)) * BATCH) * HID;
            for (int i = tid; i < 32 * 128; i += 256) {
                int b = i >> 7; int kq = (i & 127) << 2;
                *(float4*)&h_s[b * STRIDE + kq] = *(const float4*)&hp[(size_t)b * HID + kq];
            }
        }
        __syncthreads();   // also orders the one-time w_s load on the first iteration

        // ---- partial gate dot-products ----
        float acc[32];
#pragma unroll
        for (int b = 0; b < 32; b++) acc[b] = 0.f;
        const float* wp  = w_s + col * STRIDE + ksub * 32;
        const float* hpk = h_s + ksub * 32;
#pragma unroll
        for (int kq = 0; kq < 32; kq += 4) {
            float4 w4 = *(const float4*)(wp + kq);
#pragma unroll
            for (int b = 0; b < 32; b++) {
                float4 h4 = *(const float4*)(hpk + (size_t)b * STRIDE + kq);
                acc[b] += h4.x * w4.x + h4.y * w4.y + h4.z * w4.z + h4.w * w4.w;
            }
        }
        __syncthreads();   // done reading h_s; safe to overlay with partials

        // ---- write partials (coalesced STS.128) ----
#pragma unroll
        for (int b4 = 0; b4 < 8; b4++) {
            *(float4*)&part[ksub * STRIDE + b4 * 64 + col * 4] =
                make_float4(acc[b4 * 4 + 0], acc[b4 * 4 + 1], acc[b4 * 4 + 2], acc[b4 * 4 + 3]);
        }
        __syncthreads();

        // ---- reduce + activations + outputs (threads 0..127: one (b,j) each) ----
        if (tid < 128) {
            int j = jblk * 4 + ajj;
            const float* pre_t = g_pre + ((size_t)t * BATCH + ab) * G4;
            float gs[4];
#pragma unroll
            for (int g = 0; g < 4; g++) {
                int c = g * 4 + ajj;
                float s = 0.f;
#pragma unroll
                for (int ks = 0; ks < 16; ks++)
                    s += part[ks * STRIDE + (ab >> 2) * 64 + c * 4 + (ab & 3)];
                gs[g] = s + pre_t[g * HID + j];
            }
            float i_t = 1.f / (1.f + __expf(-gs[0]));
            float f_t = 1.f / (1.f + __expf(-gs[1]));
            float g_t = tanhf(gs[2]);
            float o_t = 1.f / (1.f + __expf(-gs[3]));
            float c_new = f_t * c_state + i_t * g_t;
            float h_new = o_t * tanhf(c_new);
            c_state = c_new;
            size_t oidx = ((size_t)(layer * T_STEPS + t) * BATCH + ab) * HID + j;
            out[oidx]            = h_new;
            out[SECT + oidx]     = c_new;
            out[2 * SECT + oidx] = i_t;
            out[3 * SECT + oidx] = f_t;
            out[4 * SECT + oidx] = g_t;
            out[5 * SECT + oidx] = o_t;
        }

        // ---- grid-wide barrier (all 128 blocks co-resident: grid <= #SMs) ----
        __threadfence();
        __syncthreads();
        if (tid == 0) {
            atomicAdd(&g_bar, 1u);
            phase++;
            const unsigned target = phase * gridDim.x;
            while (*(volatile unsigned*)&g_bar < target) __nanosleep(64);
        }
        __syncthreads();
    }
}

// ---------------- launch ----------------
extern "C" void kernel_launch(void* const* d_in, const int* in_sizes, int n_in,
                              void* d_out, int out_size)
{
    (void)in_sizes; (void)n_in; (void)out_size;
    const float* x    = (const float*)d_in[0];   // [T,B,I]
    const float* w_ih = (const float*)d_in[1];   // [L,4H,I]
    const float* w_hh = (const float*)d_in[2];   // [L,4H,H]
    const float* b_ih = (const float*)d_in[3];   // [L,4H]
    const float* b_hh = (const float*)d_in[4];   // [L,4H]
    float* out = (float*)d_out;

    const int smem = 48 * STRIDE * 4;  // w_s + h_s = 99072 bytes
    cudaFuncSetAttribute(lstm_layer, cudaFuncAttributeMaxDynamicSharedMemorySize, smem);

    dim3 gg(T_STEPS * BATCH / 64, G4 / 64);  // (256, 32)
    for (int l = 0; l < 2; l++) {
        const float* A = (l == 0) ? x : out;  // layer-1 input = layer-0 h (offset 0 of out)
        pre_gemm<<<gg, 256>>>(A, w_ih + (size_t)l * G4 * HID,
                              b_ih + (size_t)l * G4, b_hh + (size_t)l * G4);
        reset_bar<<<1, 1>>>();
        lstm_layer<<<NBLK, 256, smem>>>(l, w_hh + (size_t)l * G4 * HID, out);
    }
}

// round 4
// speedup vs baseline: 1.8456x; 1.8456x over previous
#include <cuda_runtime.h>
#include <cstdint>

#define T_STEPS 512
#define BATCH   32
#define HID     512
#define G4      2048
#define NBLK    128
#define STRIDE  516
#define PSTR    20                // partials row stride (floats): 80B, 16B-aligned
#define SECT    ((size_t)2 * T_STEPS * BATCH * HID)

// ---------------- device scratch ----------------
__device__ __align__(16) float g_pre[(size_t)T_STEPS * BATCH * G4];  // pre-projection, current layer
__device__ __align__(16) float g_hbuf[2][BATCH * HID];               // h ring buffer (L2-hot)
__device__ unsigned g_bar;

__global__ void reset_bar() { g_bar = 0u; }

// ---------------- pre-projection GEMM: 128x128 tile, k=8 double-buffered ----------------
// g_pre[row][g] = sum_k A[row][k] * W[g][k] + bih[g] + bhh[g]
__global__ void __launch_bounds__(256) pre_gemm(
    const float* __restrict__ A, const float* __restrict__ W,
    const float* __restrict__ bih, const float* __restrict__ bhh)
{
    __shared__ float As[2][8][132];
    __shared__ float Ws[2][8][132];
    const int tid  = threadIdx.x;
    const int brow = blockIdx.x * 128;
    const int bcol = blockIdx.y * 128;
    const int lr   = tid >> 1;          // 0..127
    const int lkc  = (tid & 1) << 2;    // 0 or 4
    const int tm   = (tid >> 4) << 3;   // 0..120
    const int tn   = (tid & 15) << 3;   // 0..120

    float acc[8][8];
#pragma unroll
    for (int i = 0; i < 8; i++)
#pragma unroll
        for (int j = 0; j < 8; j++) acc[i][j] = 0.f;

    const float* Aip = A + (size_t)(brow + lr) * HID + lkc;
    const float* Wip = W + (size_t)(bcol + lr) * HID + lkc;

    // prologue: stage 0
    {
        float4 a4 = *(const float4*)Aip;
        float4 w4 = *(const float4*)Wip;
        As[0][lkc + 0][lr] = a4.x; As[0][lkc + 1][lr] = a4.y;
        As[0][lkc + 2][lr] = a4.z; As[0][lkc + 3][lr] = a4.w;
        Ws[0][lkc + 0][lr] = w4.x; Ws[0][lkc + 1][lr] = w4.y;
        Ws[0][lkc + 2][lr] = w4.z; Ws[0][lkc + 3][lr] = w4.w;
    }

    int buf = 0;
    for (int k0 = 0; k0 < HID; k0 += 8) {
        const bool nxt = (k0 + 8) < HID;
        float4 na, nw;
        if (nxt) {
            na = *(const float4*)(Aip + k0 + 8);
            nw = *(const float4*)(Wip + k0 + 8);
        }
        __syncthreads();   // stores to As/Ws[buf] visible; prev reads of buf^1 done
#pragma unroll
        for (int kk = 0; kk < 8; kk++) {
            float4 a0 = *(const float4*)&As[buf][kk][tm];
            float4 a1 = *(const float4*)&As[buf][kk][tm + 4];
            float4 b0 = *(const float4*)&Ws[buf][kk][tn];
            float4 b1 = *(const float4*)&Ws[buf][kk][tn + 4];
            float av[8] = {a0.x, a0.y, a0.z, a0.w, a1.x, a1.y, a1.z, a1.w};
            float bv[8] = {b0.x, b0.y, b0.z, b0.w, b1.x, b1.y, b1.z, b1.w};
#pragma unroll
            for (int i = 0; i < 8; i++)
#pragma unroll
                for (int j = 0; j < 8; j++) acc[i][j] += av[i] * bv[j];
        }
        if (nxt) {
            const int nb = buf ^ 1;
            As[nb][lkc + 0][lr] = na.x; As[nb][lkc + 1][lr] = na.y;
            As[nb][lkc + 2][lr] = na.z; As[nb][lkc + 3][lr] = na.w;
            Ws[nb][lkc + 0][lr] = nw.x; Ws[nb][lkc + 1][lr] = nw.y;
            Ws[nb][lkc + 2][lr] = nw.z; Ws[nb][lkc + 3][lr] = nw.w;
        }
        buf ^= 1;
    }

    float bb[8];
#pragma unroll
    for (int j = 0; j < 8; j++) { int g = bcol + tn + j; bb[j] = bih[g] + bhh[g]; }
#pragma unroll
    for (int i = 0; i < 8; i++) {
        size_t ro = (size_t)(brow + tm + i) * G4 + bcol + tn;
        *(float4*)&g_pre[ro] = make_float4(acc[i][0] + bb[0], acc[i][1] + bb[1],
                                           acc[i][2] + bb[2], acc[i][3] + bb[3]);
        *(float4*)&g_pre[ro + 4] = make_float4(acc[i][4] + bb[4], acc[i][5] + bb[5],
                                               acc[i][6] + bb[6], acc[i][7] + bb[7]);
    }
}

// ---------------- persistent recurrence kernel (one launch per layer) ----------------
// 512 threads: col = tid&15 (gate*4+jj), ksub = (tid>>4)&15, bh = tid>>8.
// Whh chunk (32 floats) lives in registers for the whole layer.
__global__ void __launch_bounds__(512, 1) lstm_layer(
    int layer, const float* __restrict__ whh, float* __restrict__ out)
{
    extern __shared__ float sm[];
    float* h_s  = sm;                   // [32][STRIDE]
    float* part = sm + 32 * STRIDE;     // [512][PSTR]

    const int tid  = threadIdx.x;
    const int col  = tid & 15;
    const int ksub = (tid >> 4) & 15;
    const int bh   = tid >> 8;
    const int jblk = blockIdx.x;

    // per-thread Whh chunk in registers (loaded once per layer)
    const int gate = col >> 2, jj = col & 3;
    float4 wreg[8];
    {
        const float* wp = whh + (size_t)(gate * HID + jblk * 4 + jj) * HID + ksub * 32;
#pragma unroll
        for (int q = 0; q < 8; q++) wreg[q] = *(const float4*)(wp + q * 4);
    }

    // activation threads (tid < 128): one (b, j) pair each, c in register
    const int ajj = tid & 3;
    const int ab  = (tid >> 2) & 31;
    const int aj  = jblk * 4 + ajj;
    float c_state = 0.f;

    for (int t = 0; t < T_STEPS; t++) {
        // ---- prefetch pre-projection for this step ----
        float preg[4];
        if (tid < 128) {
            const float* pp = g_pre + ((size_t)t * BATCH + ab) * G4 + aj;
#pragma unroll
            for (int g = 0; g < 4; g++) preg[g] = __ldg(pp + g * HID);
        }

        // ---- stage h_{t-1} into SMEM (ring buffer, L2-hot, bypass L1) ----
        if (t == 0) {
#pragma unroll
            for (int q = 0; q < 8; q++) {
                int lin = q * 512 + tid;
                int b = lin >> 7, kq = (lin & 127) << 2;
                *(float4*)&h_s[b * STRIDE + kq] = make_float4(0.f, 0.f, 0.f, 0.f);
            }
        } else {
            const float* hb = g_hbuf[t & 1];
#pragma unroll
            for (int q = 0; q < 8; q++) {
                int lin = q * 512 + tid;
                int b = lin >> 7, kq = (lin & 127) << 2;
                *(float4*)&h_s[b * STRIDE + kq] = __ldcg((const float4*)(hb + b * 512 + kq));
            }
        }
        __syncthreads();

        // ---- partial gate dot-products: 512 FFMA + 128 LDS.128 (16-way bcast) ----
        float acc[16];
#pragma unroll
        for (int b = 0; b < 16; b++) acc[b] = 0.f;
        const float* hp = h_s + (size_t)(bh * 16) * STRIDE + ksub * 32;
#pragma unroll
        for (int q = 0; q < 8; q++) {
            float4 w4 = wreg[q];
#pragma unroll
            for (int b = 0; b < 16; b++) {
                float4 h4 = *(const float4*)(hp + (size_t)b * STRIDE + q * 4);
                acc[b] += h4.x * w4.x + h4.y * w4.y + h4.z * w4.z + h4.w * w4.w;
            }
        }

        // ---- write partials (PSTR=20 floats = 80B rows -> 16B-aligned STS.128) ----
        float* pr = part + (size_t)(((ksub * 2 + bh) * 16 + col) * PSTR);
#pragma unroll
        for (int b4 = 0; b4 < 4; b4++)
            *(float4*)(pr + b4 * 4) = make_float4(acc[b4 * 4 + 0], acc[b4 * 4 + 1],
                                                  acc[b4 * 4 + 2], acc[b4 * 4 + 3]);
        __syncthreads();

        // ---- reduce + activations + outputs ----
        if (tid < 128) {
            const int bhi = ab >> 4, bl = ab & 15;
            float gs[4];
#pragma unroll
            for (int g = 0; g < 4; g++) {
                int c = g * 4 + ajj;
                float s = preg[g];
#pragma unroll
                for (int ks = 0; ks < 16; ks++)
                    s += part[((ks * 2 + bhi) * 16 + c) * PSTR + bl];
                gs[g] = s;
            }
            float i_t = 1.f / (1.f + __expf(-gs[0]));
            float f_t = 1.f / (1.f + __expf(-gs[1]));
            float g_t = __fdividef(2.f, 1.f + __expf(-2.f * gs[2])) - 1.f;
            float o_t = 1.f / (1.f + __expf(-gs[3]));
            float c_new = f_t * c_state + i_t * g_t;
            float tc    = __fdividef(2.f, 1.f + __expf(-2.f * c_new)) - 1.f;
            float h_new = o_t * tc;
            c_state = c_new;
            size_t oidx = ((size_t)(layer * T_STEPS + t) * BATCH + ab) * HID + aj;
            out[oidx]            = h_new;
            out[SECT + oidx]     = c_new;
            out[2 * SECT + oidx] = i_t;
            out[3 * SECT + oidx] = f_t;
            out[4 * SECT + oidx] = g_t;
            out[5 * SECT + oidx] = o_t;
            g_hbuf[(t + 1) & 1][ab * HID + aj] = h_new;
        }

        // ---- grid barrier: release-red + acquire-spin ----
        __syncthreads();
        if (tid == 0) {
            asm volatile("red.release.gpu.global.add.u32 [%0], 1;" :: "l"(&g_bar) : "memory");
            const unsigned target = (unsigned)(t + 1) * NBLK;
            unsigned v;
            do {
                asm volatile("ld.acquire.gpu.global.u32 %0, [%1];" : "=r"(v) : "l"(&g_bar) : "memory");
            } while (v < target);
        }
        __syncthreads();
    }
}

// ---------------- launch ----------------
extern "C" void kernel_launch(void* const* d_in, const int* in_sizes, int n_in,
                              void* d_out, int out_size)
{
    (void)in_sizes; (void)n_in; (void)out_size;
    const float* x    = (const float*)d_in[0];
    const float* w_ih = (const float*)d_in[1];
    const float* w_hh = (const float*)d_in[2];
    const float* b_ih = (const float*)d_in[3];
    const float* b_hh = (const float*)d_in[4];
    float* out = (float*)d_out;

    const int smem = (32 * STRIDE + 512 * PSTR) * 4;  // 107008 B
    cudaFuncSetAttribute(lstm_layer, cudaFuncAttributeMaxDynamicSharedMemorySize, smem);

    dim3 gg(T_STEPS * BATCH / 128, G4 / 128);  // (128, 16)
    for (int l = 0; l < 2; l++) {
        const float* A = (l == 0) ? x : out;   // layer-1 input = layer-0 h (offset 0)
        pre_gemm<<<gg, 256>>>(A, w_ih + (size_t)l * G4 * HID,
                              b_ih + (size_t)l * G4, b_hh + (size_t)l * G4);
        reset_bar<<<1, 1>>>();
        lstm_layer<<<NBLK, 512, smem>>>(l, w_hh + (size_t)l * G4 * HID, out);
    }
}

// round 6
// speedup vs baseline: 2.2208x; 1.2033x over previous
#include <cuda_runtime.h>
#include <cstdint>

#define T_STEPS 512
#define BATCH   32
#define HID     512
#define G4      2048
#define NBLK    128
#define STRIDE  516
#define PSTR    20
#define SECT    ((size_t)2 * T_STEPS * BATCH * HID)

// ---------------- device scratch ----------------
__device__ __align__(16) float g_pre[(size_t)T_STEPS * BATCH * G4];
__device__ __align__(16) float g_hbuf[2][BATCH * HID];
__device__ unsigned g_bar;

__global__ void reset_bar() { g_bar = 0u; }

// ================= pre-projection GEMM: tf32 tensor cores =================
// g_pre[row][g] = sum_k A[row][k] * W[g][k] + bih[g] + bhh[g]
// Block tile 128x128, 8 warps (warp tile 32x64), k-chunk 16, double-buffered.
// SMEM layout [k][m] stride 136 -> conflict-free fragment loads.
#define KSTR 136

__device__ __forceinline__ unsigned f2tf32(float f) {
    unsigned u;
    asm("cvt.rna.tf32.f32 %0, %1;" : "=r"(u) : "f"(f));
    return u;
}

__device__ __forceinline__ void mma_tf32(float c[4], const unsigned a[4],
                                         unsigned b0, unsigned b1) {
    asm volatile(
        "mma.sync.aligned.m16n8k8.row.col.f32.tf32.tf32.f32 "
        "{%0,%1,%2,%3}, {%4,%5,%6,%7}, {%8,%9}, {%0,%1,%2,%3};"
        : "+f"(c[0]), "+f"(c[1]), "+f"(c[2]), "+f"(c[3])
        : "r"(a[0]), "r"(a[1]), "r"(a[2]), "r"(a[3]), "r"(b0), "r"(b1));
}

__global__ void __launch_bounds__(256) pre_gemm_tc(
    const float* __restrict__ A, const float* __restrict__ W,
    const float* __restrict__ bih, const float* __restrict__ bhh)
{
    __shared__ unsigned As[2][16 * KSTR];
    __shared__ unsigned Ws[2][16 * KSTR];

    const int tid  = threadIdx.x;
    const int brow = blockIdx.x * 128;
    const int bcol = blockIdx.y * 128;
    const int lane = tid & 31, wid = tid >> 5;
    const int grp  = lane >> 2, tg = lane & 3;
    const int m0w  = (wid & 3) * 32;
    const int n0w  = (wid >> 2) * 64;

    // staging map: 512 float4 per 128x16 tile; thread handles f4idx = tid, tid+256
    // f4idx -> row = f4idx>>2 (0..127), kq = (f4idx&3)*4  (coalesced 64B/row-group)
    const int sr0 = tid >> 2,        sk0 = (tid & 3) << 2;
    const int sr1 = (tid + 256) >> 2, sk1 = sk0;  // (tid+256)&3 == tid&3

    float c[2][8][4];
#pragma unroll
    for (int mt = 0; mt < 2; mt++)
#pragma unroll
        for (int nt = 0; nt < 8; nt++)
#pragma unroll
            for (int i = 0; i < 4; i++) c[mt][nt][i] = 0.f;

    const float* Ap = A + (size_t)brow * HID;
    const float* Wp = W + (size_t)bcol * HID;

    // prologue: stage k-chunk 0 into buf 0
    {
        float4 a0 = *(const float4*)(Ap + (size_t)sr0 * HID + sk0);
        float4 a1 = *(const float4*)(Ap + (size_t)sr1 * HID + sk1);
        float4 w0 = *(const float4*)(Wp + (size_t)sr0 * HID + sk0);
        float4 w1 = *(const float4*)(Wp + (size_t)sr1 * HID + sk1);
        As[0][(sk0 + 0) * KSTR + sr0] = f2tf32(a0.x);
        As[0][(sk0 + 1) * KSTR + sr0] = f2tf32(a0.y);
        As[0][(sk0 + 2) * KSTR + sr0] = f2tf32(a0.z);
        As[0][(sk0 + 3) * KSTR + sr0] = f2tf32(a0.w);
        As[0][(sk1 + 0) * KSTR + sr1] = f2tf32(a1.x);
        As[0][(sk1 + 1) * KSTR + sr1] = f2tf32(a1.y);
        As[0][(sk1 + 2) * KSTR + sr1] = f2tf32(a1.z);
        As[0][(sk1 + 3) * KSTR + sr1] = f2tf32(a1.w);
        Ws[0][(sk0 + 0) * KSTR + sr0] = f2tf32(w0.x);
        Ws[0][(sk0 + 1) * KSTR + sr0] = f2tf32(w0.y);
        Ws[0][(sk0 + 2) * KSTR + sr0] = f2tf32(w0.z);
        Ws[0][(sk0 + 3) * KSTR + sr0] = f2tf32(w0.w);
        Ws[0][(sk1 + 0) * KSTR + sr1] = f2tf32(w1.x);
        Ws[0][(sk1 + 1) * KSTR + sr1] = f2tf32(w1.y);
        Ws[0][(sk1 + 2) * KSTR + sr1] = f2tf32(w1.z);
        Ws[0][(sk1 + 3) * KSTR + sr1] = f2tf32(w1.w);
    }

    int buf = 0;
    for (int kt = 0; kt < 32; kt++) {
        const bool nxt = (kt + 1) < 32;
        float4 na0, na1, nw0, nw1;
        if (nxt) {
            const int k0 = (kt + 1) * 16;
            na0 = *(const float4*)(Ap + (size_t)sr0 * HID + k0 + sk0);
            na1 = *(const float4*)(Ap + (size_t)sr1 * HID + k0 + sk1);
            nw0 = *(const float4*)(Wp + (size_t)sr0 * HID + k0 + sk0);
            nw1 = *(const float4*)(Wp + (size_t)sr1 * HID + k0 + sk1);
        }
        __syncthreads();   // staging of buf visible; prior compute on buf done

        const unsigned* Asb = As[buf];
        const unsigned* Wsb = Ws[buf];
#pragma unroll
        for (int k8 = 0; k8 < 16; k8 += 8) {
            unsigned af[2][4];
#pragma unroll
            for (int mt = 0; mt < 2; mt++) {
                const int m = m0w + mt * 16 + grp;
                af[mt][0] = Asb[(k8 + tg) * KSTR + m];
                af[mt][1] = Asb[(k8 + tg) * KSTR + m + 8];
                af[mt][2] = Asb[(k8 + tg + 4) * KSTR + m];
                af[mt][3] = Asb[(k8 + tg + 4) * KSTR + m + 8];
            }
#pragma unroll
            for (int nt = 0; nt < 8; nt++) {
                const int n = n0w + nt * 8 + grp;
                unsigned b0 = Wsb[(k8 + tg) * KSTR + n];
                unsigned b1 = Wsb[(k8 + tg + 4) * KSTR + n];
                mma_tf32(c[0][nt], af[0], b0, b1);
                mma_tf32(c[1][nt], af[1], b0, b1);
            }
        }

        if (nxt) {
            __syncthreads();   // all compute on buf^1 from prev iter finished
            const int nb = buf ^ 1;
            As[nb][(sk0 + 0) * KSTR + sr0] = f2tf32(na0.x);
            As[nb][(sk0 + 1) * KSTR + sr0] = f2tf32(na0.y);
            As[nb][(sk0 + 2) * KSTR + sr0] = f2tf32(na0.z);
            As[nb][(sk0 + 3) * KSTR + sr0] = f2tf32(na0.w);
            As[nb][(sk1 + 0) * KSTR + sr1] = f2tf32(na1.x);
            As[nb][(sk1 + 1) * KSTR + sr1] = f2tf32(na1.y);
            As[nb][(sk1 + 2) * KSTR + sr1] = f2tf32(na1.z);
            As[nb][(sk1 + 3) * KSTR + sr1] = f2tf32(na1.w);
            Ws[nb][(sk0 + 0) * KSTR + sr0] = f2tf32(nw0.x);
            Ws[nb][(sk0 + 1) * KSTR + sr0] = f2tf32(nw0.y);
            Ws[nb][(sk0 + 2) * KSTR + sr0] = f2tf32(nw0.z);
            Ws[nb][(sk0 + 3) * KSTR + sr0] = f2tf32(nw0.w);
            Ws[nb][(sk1 + 0) * KSTR + sr1] = f2tf32(nw1.x);
            Ws[nb][(sk1 + 1) * KSTR + sr1] = f2tf32(nw1.y);
            Ws[nb][(sk1 + 2) * KSTR + sr1] = f2tf32(nw1.z);
            Ws[nb][(sk1 + 3) * KSTR + sr1] = f2tf32(nw1.w);
        }
        buf ^= 1;
    }

    // epilogue: add bias, write float2 pairs
#pragma unroll
    for (int nt = 0; nt < 8; nt++) {
        const int col = bcol + n0w + nt * 8 + 2 * tg;
        const float bb0 = bih[col] + bhh[col];
        const float bb1 = bih[col + 1] + bhh[col + 1];
#pragma unroll
        for (int mt = 0; mt < 2; mt++) {
            const int row = brow + m0w + mt * 16 + grp;
            float2 o0 = make_float2(c[mt][nt][0] + bb0, c[mt][nt][1] + bb1);
            float2 o1 = make_float2(c[mt][nt][2] + bb0, c[mt][nt][3] + bb1);
            *(float2*)&g_pre[(size_t)row * G4 + col]       = o0;
            *(float2*)&g_pre[(size_t)(row + 8) * G4 + col] = o1;
        }
    }
}

// ================= persistent recurrence kernel (fp32, packed f32x2 FMA) =================
#define FMA2(d, a, b) \
    asm("fma.rn.f32x2 %0, %1, %2, %0;" : "+l"(d) : "l"(a), "l"(b))

__global__ void __launch_bounds__(512, 1) lstm_layer(
    int layer, const float* __restrict__ whh, float* __restrict__ out)
{
    extern __shared__ float sm[];
    float* h_s  = sm;                   // [32][STRIDE]
    float* part = sm + 32 * STRIDE;     // [512][PSTR]

    const int tid  = threadIdx.x;
    const int col  = tid & 15;
    const int ksub = (tid >> 4) & 15;
    const int bh   = tid >> 8;
    const int jblk = blockIdx.x;

    // per-thread Whh chunk as packed f32x2 pairs (loaded once per layer)
    const int gate = col >> 2, jj = col & 3;
    ulonglong2 wq[8];
    {
        const float* wp = whh + (size_t)(gate * HID + jblk * 4 + jj) * HID + ksub * 32;
#pragma unroll
        for (int q = 0; q < 8; q++) wq[q] = *(const ulonglong2*)(wp + q * 4);
    }

    const int ajj = tid & 3;
    const int ab  = (tid >> 2) & 31;
    const int aj  = jblk * 4 + ajj;
    float c_state = 0.f;

    for (int t = 0; t < T_STEPS; t++) {
        // ---- prefetch pre-projection for this step ----
        float preg[4];
        if (tid < 128) {
            const float* pp = g_pre + ((size_t)t * BATCH + ab) * G4 + aj;
#pragma unroll
            for (int g = 0; g < 4; g++) preg[g] = __ldg(pp + g * HID);
        }

        // ---- stage h_{t-1} into SMEM ----
        if (t == 0) {
#pragma unroll
            for (int q = 0; q < 8; q++) {
                int lin = q * 512 + tid;
                int b = lin >> 7, kq = (lin & 127) << 2;
                *(float4*)&h_s[b * STRIDE + kq] = make_float4(0.f, 0.f, 0.f, 0.f);
            }
        } else {
            const float* hb = g_hbuf[t & 1];
#pragma unroll
            for (int q = 0; q < 8; q++) {
                int lin = q * 512 + tid;
                int b = lin >> 7, kq = (lin & 127) << 2;
                *(float4*)&h_s[b * STRIDE + kq] = __ldcg((const float4*)(hb + b * 512 + kq));
            }
        }
        __syncthreads();

        // ---- partial dot-products: 256 fma.rn.f32x2 + 128 LDS.128 per thread ----
        unsigned long long acc2[16];
#pragma unroll
        for (int b = 0; b < 16; b++) acc2[b] = 0ull;
        const float* hp = h_s + (size_t)(bh * 16) * STRIDE + ksub * 32;
#pragma unroll
        for (int q = 0; q < 8; q++) {
            const unsigned long long wlo = wq[q].x, whi = wq[q].y;
#pragma unroll
            for (int b = 0; b < 16; b++) {
                ulonglong2 h2 = *(const ulonglong2*)(hp + (size_t)b * STRIDE + q * 4);
                FMA2(acc2[b], h2.x, wlo);
                FMA2(acc2[b], h2.y, whi);
            }
        }
        float accf[16];
#pragma unroll
        for (int b = 0; b < 16; b++) {
            float lo = __uint_as_float((unsigned)acc2[b]);
            float hi = __uint_as_float((unsigned)(acc2[b] >> 32));
            accf[b] = lo + hi;
        }

        // ---- write partials (80B rows, 16B-aligned STS.128) ----
        float* pr = part + (size_t)(((ksub * 2 + bh) * 16 + col) * PSTR);
#pragma unroll
        for (int b4 = 0; b4 < 4; b4++)
            *(float4*)(pr + b4 * 4) = make_float4(accf[b4 * 4 + 0], accf[b4 * 4 + 1],
                                                  accf[b4 * 4 + 2], accf[b4 * 4 + 3]);
        __syncthreads();

        // ---- reduce + activations + outputs ----
        if (tid < 128) {
            const int bhi = ab >> 4, bl = ab & 15;
            float gs[4];
#pragma unroll
            for (int g = 0; g < 4; g++) {
                int c = g * 4 + ajj;
                float s = preg[g];
#pragma unroll
                for (int ks = 0; ks < 16; ks++)
                    s += part[((ks * 2 + bhi) * 16 + c) * PSTR + bl];
                gs[g] = s;
            }
            float i_t = 1.f / (1.f + __expf(-gs[0]));
            float f_t = 1.f / (1.f + __expf(-gs[1]));
            float g_t = __fdividef(2.f, 1.f + __expf(-2.f * gs[2])) - 1.f;
            float o_t = 1.f / (1.f + __expf(-gs[3]));
            float c_new = f_t * c_state + i_t * g_t;
            float tc    = __fdividef(2.f, 1.f + __expf(-2.f * c_new)) - 1.f;
            float h_new = o_t * tc;
            c_state = c_new;
            size_t oidx = ((size_t)(layer * T_STEPS + t) * BATCH + ab) * HID + aj;
            out[oidx]            = h_new;
            out[SECT + oidx]     = c_new;
            out[2 * SECT + oidx] = i_t;
            out[3 * SECT + oidx] = f_t;
            out[4 * SECT + oidx] = g_t;
            out[5 * SECT + oidx] = o_t;
            g_hbuf[(t + 1) & 1][ab * HID + aj] = h_new;
        }

        // ---- grid barrier: release-red + acquire-spin ----
        __syncthreads();
        if (tid == 0) {
            asm volatile("red.release.gpu.global.add.u32 [%0], 1;" :: "l"(&g_bar) : "memory");
            const unsigned target = (unsigned)(t + 1) * NBLK;
            unsigned v;
            do {
                asm volatile("ld.acquire.gpu.global.u32 %0, [%1];" : "=r"(v) : "l"(&g_bar) : "memory");
            } while (v < target);
        }
        __syncthreads();
    }
}

// ---------------- launch ----------------
extern "C" void kernel_launch(void* const* d_in, const int* in_sizes, int n_in,
                              void* d_out, int out_size)
{
    (void)in_sizes; (void)n_in; (void)out_size;
    const float* x    = (const float*)d_in[0];
    const float* w_ih = (const float*)d_in[1];
    const float* w_hh = (const float*)d_in[2];
    const float* b_ih = (const float*)d_in[3];
    const float* b_hh = (const float*)d_in[4];
    float* out = (float*)d_out;

    const int smem = (32 * STRIDE + 512 * PSTR) * 4;  // 107008 B
    cudaFuncSetAttribute(lstm_layer, cudaFuncAttributeMaxDynamicSharedMemorySize, smem);

    dim3 gg(T_STEPS * BATCH / 128, G4 / 128);  // (128, 16)
    for (int l = 0; l < 2; l++) {
        const float* A = (l == 0) ? x : out;   // layer-1 input = layer-0 h
        pre_gemm_tc<<<gg, 256>>>(A, w_ih + (size_t)l * G4 * HID,
                                 b_ih + (size_t)l * G4, b_hh + (size_t)l * G4);
        reset_bar<<<1, 1>>>();
        lstm_layer<<<NBLK, 512, smem>>>(l, w_hh + (size_t)l * G4 * HID, out);
    }
}